// round 16
// baseline (speedup 1.0000x reference)
#include <cuda_runtime.h>
#include <cuda_bf16.h>
#include <math.h>
#include <stdint.h>

#define NB 32
#define NT 128
#define NF 128

#define SP 136                   // bf16 per row (128 + 8 pad); SP*2=272B (16B-aligned rows)
#define TILE_HI   (128 * SP * 2) // 34816 B
#define TILE_PAIR (2 * TILE_HI)  // 69632 B
#define STRIP_HI  (32 * SP * 2)  // 8704 B
#define STRIP_PAIR (2 * STRIP_HI)

#define NTHR 512

// Prepped weight images only (X converted inline in main now)
__device__ __align__(16) unsigned char g_Wd[TILE_PAIR];      // [j][f]
__device__ __align__(16) unsigned char g_Wk[3][TILE_PAIR];   // [u][f] zi/zc/zo

__device__ __forceinline__ float sigf(float x) { return 1.0f / (1.0f + __expf(-x)); }

// ---------------------------------------------------------------------------
// Prep: Wd + Wk f32 -> bf16 hi/lo images (4 tiles)
// ---------------------------------------------------------------------------
__global__ void prep_kernel(const float* __restrict__ Wd, const float* __restrict__ Wk)
{
    int gid = blockIdx.x * blockDim.x + threadIdx.x;
    const int total = 4 * 2048;
    for (int idx = gid; idx < total; idx += gridDim.x * blockDim.x) {
        int tile = idx >> 11;
        int r = idx & 127, chunk = (idx >> 7) & 15;
        int c0 = chunk * 8;
        float v[8];
        unsigned char* dst;
        if (tile == 0) {
#pragma unroll
            for (int q = 0; q < 8; q++) v[q] = Wd[(c0 + q) * NT + r];
            dst = g_Wd;
        } else {
            int gt = tile - 1;
            int gof = (gt == 0) ? 0 : (gt == 1 ? 256 : 384);
#pragma unroll
            for (int q = 0; q < 8; q++) v[q] = Wk[(c0 + q) * 512 + gof + r];
            dst = g_Wk[gt];
        }
        unsigned short hi[8], lo[8];
#pragma unroll
        for (int q = 0; q < 8; q++) {
            __nv_bfloat16 h = __float2bfloat16(v[q]);
            __nv_bfloat16 l = __float2bfloat16(v[q] - __bfloat162float(h));
            hi[q] = *(unsigned short*)&h;
            lo[q] = *(unsigned short*)&l;
        }
        uint32_t off = (uint32_t)(r * SP + c0) * 2;
        *(uint4*)(dst + off) = *(uint4*)hi;
        *(uint4*)(dst + TILE_HI + off) = *(uint4*)lo;
    }
}

// ---------------------------------------------------------------------------
// PTX helpers (all sm_80-baseline, no arch-feature gate)
// ---------------------------------------------------------------------------
__device__ __forceinline__ void mma16816(float* d, uint32_t a0, uint32_t a1,
                                         uint32_t a2, uint32_t a3,
                                         uint32_t b0, uint32_t b1) {
    asm volatile(
        "mma.sync.aligned.m16n8k16.row.col.f32.bf16.bf16.f32 "
        "{%0,%1,%2,%3}, {%4,%5,%6,%7}, {%8,%9}, {%0,%1,%2,%3};"
        : "+f"(d[0]), "+f"(d[1]), "+f"(d[2]), "+f"(d[3])
        : "r"(a0), "r"(a1), "r"(a2), "r"(a3), "r"(b0), "r"(b1));
}
__device__ __forceinline__ uint32_t lds32(const __nv_bfloat16* p) {
    return *(const uint32_t*)p;
}
__device__ __forceinline__ void ldm_x2_t(uint32_t& r0, uint32_t& r1, uint32_t saddr) {
    asm volatile("ldmatrix.sync.aligned.m8n8.x2.trans.shared.b16 {%0,%1}, [%2];"
                 : "=r"(r0), "=r"(r1) : "r"(saddr));
}
__device__ __forceinline__ void cpa16(unsigned char* dst, const unsigned char* src) {
    uint32_t d = (uint32_t)__cvta_generic_to_shared(dst);
    asm volatile("cp.async.cg.shared.global [%0], [%1], 16;" :: "r"(d), "l"(src));
}
#define CPA_COMMIT() asm volatile("cp.async.commit_group;" ::: "memory")
#define CPA_WAIT(n)  asm volatile("cp.async.wait_group %0;" :: "n"(n) : "memory")

__device__ __forceinline__ void cpa_tile(unsigned char* dst, const unsigned char* src,
                                         int bytes, int tid) {
    for (int i = tid * 16; i < bytes; i += NTHR * 16) cpa16(dst + i, src + i);
}
__device__ __forceinline__ uint32_t pk(__nv_bfloat16 a, __nv_bfloat16 b) {
    unsigned short x = *(unsigned short*)&a, y = *(unsigned short*)&b;
    return (uint32_t)x | ((uint32_t)y << 16);
}

// SMEM layout (bytes)
#define SM_XA  0                          // XA hi/lo -> Wk1
#define SM_WK  TILE_PAIR                  // Wk0 -> Wk2
#define SM_WD  (2 * TILE_PAIR)            // 139264
#define SM_P   (SM_WD + STRIP_PAIR)       // 156672
#define SM_CTX (SM_P + STRIP_PAIR)        // 174080 (Sbuf f32 aliases pre-G2)
#define SMEM_TOTAL (SM_CTX + STRIP_PAIR)  // 191488

// hoisted-A 3-term K=128 pass, direct B loads (row-major [n][k])
__device__ __forceinline__ void gemm3h(float acc[2][4],
                                       const __nv_bfloat16* Ah, const __nv_bfloat16* Al,
                                       const __nv_bfloat16* Bh, const __nv_bfloat16* Bl,
                                       int arow, int brow0, int g, int tq) {
    const __nv_bfloat16* arh = Ah + (arow + g) * SP + 2 * tq;
    const __nv_bfloat16* arl = Al + (arow + g) * SP + 2 * tq;
#pragma unroll
    for (int k0 = 0; k0 < 128; k0 += 16) {
        uint32_t ah0 = lds32(arh + k0), ah1 = lds32(arh + 8 * SP + k0);
        uint32_t ah2 = lds32(arh + k0 + 8), ah3 = lds32(arh + 8 * SP + k0 + 8);
        uint32_t al0 = lds32(arl + k0), al1 = lds32(arl + 8 * SP + k0);
        uint32_t al2 = lds32(arl + k0 + 8), al3 = lds32(arl + 8 * SP + k0 + 8);
#pragma unroll
        for (int nt = 0; nt < 2; nt++) {
            const __nv_bfloat16* brh = Bh + (brow0 + nt * 8 + g) * SP + 2 * tq + k0;
            const __nv_bfloat16* brl = Bl + (brow0 + nt * 8 + g) * SP + 2 * tq + k0;
            uint32_t bh0 = lds32(brh), bh1 = lds32(brh + 8);
            uint32_t bl0 = lds32(brl), bl1 = lds32(brl + 8);
            mma16816(acc[nt], ah0, ah1, ah2, ah3, bh0, bh1);
            mma16816(acc[nt], ah0, ah1, ah2, ah3, bl0, bl1);
            mma16816(acc[nt], al0, al1, al2, al3, bh0, bh1);
        }
    }
}

// ---------------------------------------------------------------------------
// Main: CTA = (batch b, 32 rows i0..), 512 threads / 16 warps
// ---------------------------------------------------------------------------
__global__ __launch_bounds__(NTHR, 1)
void main_kernel(const float* __restrict__ X, const float* __restrict__ bl,
                 float* __restrict__ out)
{
    extern __shared__ unsigned char smem[];
    const int tid = threadIdx.x;
    const int w = tid >> 5, lane = tid & 31, g = lane >> 2, tq = lane & 3;
    const int b = blockIdx.y, i0 = blockIdx.x * 32;

    __nv_bfloat16* XAh = (__nv_bfloat16*)(smem + SM_XA);
    __nv_bfloat16* XAl = (__nv_bfloat16*)(smem + SM_XA + TILE_HI);
    const __nv_bfloat16* WKh = (const __nv_bfloat16*)(smem + SM_WK);
    const __nv_bfloat16* WKl = (const __nv_bfloat16*)(smem + SM_WK + TILE_HI);
    const __nv_bfloat16* WDh = (const __nv_bfloat16*)(smem + SM_WD);
    const __nv_bfloat16* WDl = (const __nv_bfloat16*)(smem + SM_WD + STRIP_HI);
    __nv_bfloat16* Ph = (__nv_bfloat16*)(smem + SM_P);
    __nv_bfloat16* Pl = (__nv_bfloat16*)(smem + SM_P + STRIP_HI);
    __nv_bfloat16* Ch = (__nv_bfloat16*)(smem + SM_CTX);
    __nv_bfloat16* Cl = (__nv_bfloat16*)(smem + SM_CTX + STRIP_HI);
    float* Sbuf = (float*)(smem + SM_CTX);   // aliases CTX; dead after softmax

    // group1: Wd strips; group2: Wk0 into WK region (overlaps G1..G2!)
    cpa_tile(smem + SM_WD, g_Wd + i0 * (SP * 2), STRIP_HI, tid);
    cpa_tile(smem + SM_WD + STRIP_HI, g_Wd + TILE_HI + i0 * (SP * 2), STRIP_HI, tid);
    CPA_COMMIT();
    cpa_tile(smem + SM_WK, g_Wk[0], TILE_PAIR, tid);
    CPA_COMMIT();

    // inline convert X[b] f32 -> XA hi/lo (coalesced float4 reads)
    {
        const float* Xb = X + b * NT * NF;
        for (int idx = tid; idx < NT * 32; idx += NTHR) {
            int t = idx >> 5, fv = idx & 31;
            float4 v = *(const float4*)&Xb[t * NF + fv * 4];
            __nv_bfloat16 h0 = __float2bfloat16(v.x), h1 = __float2bfloat16(v.y);
            __nv_bfloat16 h2 = __float2bfloat16(v.z), h3 = __float2bfloat16(v.w);
            __nv_bfloat16 e0 = __float2bfloat16(v.x - __bfloat162float(h0));
            __nv_bfloat16 e1 = __float2bfloat16(v.y - __bfloat162float(h1));
            __nv_bfloat16 e2 = __float2bfloat16(v.z - __bfloat162float(h2));
            __nv_bfloat16 e3 = __float2bfloat16(v.w - __bfloat162float(h3));
            uint2 hv = make_uint2(pk(h0, h1), pk(h2, h3));
            uint2 lv = make_uint2(pk(e0, e1), pk(e2, e3));
            *(uint2*)&XAh[t * SP + fv * 4] = hv;
            *(uint2*)&XAl[t * SP + fv * 4] = lv;
        }
    }
    CPA_WAIT(1);       // Wd resident; Wk0 may still fly
    __syncthreads();

    // ---- G1: S[t][j]. warp w: t-strip (w&7)*16, j-half (w>>3)*16 ----
    {
        float acc[2][4] = {};
        const int t0 = (w & 7) * 16, jh = (w >> 3) * 16;
        gemm3h(acc, XAh, XAl, WDh, WDl, t0, jh, g, tq);
        const int r0 = t0 + g;
#pragma unroll
        for (int nt = 0; nt < 2; nt++) {
            int c = jh + nt * 8 + 2 * tq;
            Sbuf[r0 * 33 + c]     = acc[nt][0];
            Sbuf[r0 * 33 + c + 1] = acc[nt][1];
            Sbuf[(r0 + 8) * 33 + c]     = acc[nt][2];
            Sbuf[(r0 + 8) * 33 + c + 1] = acc[nt][3];
        }
    }
    __syncthreads();

    // ---- softmax over t per column j (16 warps x 2 cols); P[j][t] hi/lo ----
    {
#pragma unroll
        for (int c = 0; c < 2; c++) {
            const int j = w * 2 + c;
            float v[4];
#pragma unroll
            for (int r = 0; r < 4; r++) v[r] = Sbuf[(lane + 32 * r) * 33 + j];
            float m = fmaxf(fmaxf(v[0], v[1]), fmaxf(v[2], v[3]));
#pragma unroll
            for (int o = 16; o > 0; o >>= 1) m = fmaxf(m, __shfl_xor_sync(0xffffffffu, m, o));
            float s = 0.f;
#pragma unroll
            for (int r = 0; r < 4; r++) { v[r] = __expf(v[r] - m); s += v[r]; }
#pragma unroll
            for (int o = 16; o > 0; o >>= 1) s += __shfl_xor_sync(0xffffffffu, s, o);
            const float inv = 1.0f / s;
#pragma unroll
            for (int r = 0; r < 4; r++) {
                float a = v[r] * inv;
                __nv_bfloat16 h = __float2bfloat16(a);
                __nv_bfloat16 l = __float2bfloat16(a - __bfloat162float(h));
                Ph[j * SP + lane + 32 * r] = h;
                Pl[j * SP + lane + 32 * r] = l;
            }
        }
    }
    __syncthreads();   // Sbuf dead; P visible

    // ---- G2: CTX[i][f] = P @ X. A=P direct; B=XA via ldmatrix.trans ----
    const int mw = (w & 1) * 16;
    const int n0 = (w >> 1) * 16;
    {
        uint32_t xaH = (uint32_t)__cvta_generic_to_shared(smem + SM_XA)
                       + (uint32_t)((lane & 15) * SP * 2);
        uint32_t xaL = xaH + TILE_HI;
        const __nv_bfloat16* arh = Ph + (mw + g) * SP + 2 * tq;
        const __nv_bfloat16* arl = Pl + (mw + g) * SP + 2 * tq;
        float acc[2][4] = {};
#pragma unroll
        for (int k0 = 0; k0 < 128; k0 += 16) {
            uint32_t ah0 = lds32(arh + k0), ah1 = lds32(arh + 8 * SP + k0);
            uint32_t ah2 = lds32(arh + k0 + 8), ah3 = lds32(arh + 8 * SP + k0 + 8);
            uint32_t al0 = lds32(arl + k0), al1 = lds32(arl + 8 * SP + k0);
            uint32_t al2 = lds32(arl + k0 + 8), al3 = lds32(arl + 8 * SP + k0 + 8);
#pragma unroll
            for (int nt = 0; nt < 2; nt++) {
                uint32_t off = (uint32_t)((k0 * SP + n0 + nt * 8) * 2);
                uint32_t bh0, bh1, bl0, bl1;
                ldm_x2_t(bh0, bh1, xaH + off);
                ldm_x2_t(bl0, bl1, xaL + off);
                mma16816(acc[nt], ah0, ah1, ah2, ah3, bh0, bh1);
                mma16816(acc[nt], ah0, ah1, ah2, ah3, bl0, bl1);
                mma16816(acc[nt], al0, al1, al2, al3, bh0, bh1);
            }
        }
        const int r0 = mw + g;
#pragma unroll
        for (int nt = 0; nt < 2; nt++) {
            int c = n0 + nt * 8 + 2 * tq;
#pragma unroll
            for (int q = 0; q < 4; q++) {
                int rr = (q < 2) ? r0 : r0 + 8;
                int cc = c + (q & 1);
                float x = acc[nt][q];
                __nv_bfloat16 h = __float2bfloat16(x);
                __nv_bfloat16 l = __float2bfloat16(x - __bfloat162float(h));
                Ch[rr * SP + cc] = h;
                Cl[rr * SP + cc] = l;
            }
        }
    }
    __syncthreads();   // XA reads done; CTX visible

    // prefetch Wk1 into (dead) XA region; overlaps gate0
    cpa_tile(smem + SM_XA, g_Wk[1], TILE_PAIR, tid);
    CPA_COMMIT();

    CPA_WAIT(1);       // Wk0 resident (Wk1 pending)
    __syncthreads();
    float aI[2][4] = {}, aC[2][4] = {}, aO[2][4] = {};
    gemm3h(aI, Ch, Cl, WKh, WKl, mw, n0, g, tq);
    __syncthreads();   // WK reads done

    // prefetch Wk2 into WK region; overlaps gate1
    cpa_tile(smem + SM_WK, g_Wk[2], TILE_PAIR, tid);
    CPA_COMMIT();

    CPA_WAIT(1);       // Wk1 resident (Wk2 pending)
    __syncthreads();
    gemm3h(aC, Ch, Cl, (const __nv_bfloat16*)XAh, (const __nv_bfloat16*)XAl, mw, n0, g, tq);

    CPA_WAIT(0);       // Wk2 resident
    __syncthreads();
    gemm3h(aO, Ch, Cl, WKh, WKl, mw, n0, g, tq);

    // ---- epilogue: bias + LSTM cell ----
    {
        const int r0 = i0 + mw + g;
#pragma unroll
        for (int nt = 0; nt < 2; nt++) {
            int u0 = n0 + nt * 8 + 2 * tq;
#pragma unroll
            for (int q = 0; q < 4; q++) {
                int rr = (q < 2) ? r0 : r0 + 8;
                int u = u0 + (q & 1);
                float zi = aI[nt][q] + __ldg(&bl[u]);
                float zc = aC[nt][q] + __ldg(&bl[256 + u]);
                float zo = aO[nt][q] + __ldg(&bl[384 + u]);
                float cell = sigf(zi) * tanhf(zc);
                out[(b * NT + rr) * NF + u] = sigf(zo) * tanhf(cell);
            }
        }
    }
}

extern "C" void kernel_launch(void* const* d_in, const int* in_sizes, int n_in,
                              void* d_out, int out_size)
{
    const float* X  = (const float*)d_in[0];   // (32,128,128)
    const float* Wd = (const float*)d_in[1];   // (256,128), rows [0:128)
    const float* Wk = (const float*)d_in[3];   // (128,512)
    const float* bl = (const float*)d_in[5];   // (512,)
    float* out = (float*)d_out;                // (32,128,128)

    prep_kernel<<<16, 512>>>(Wd, Wk);
    cudaFuncSetAttribute(main_kernel, cudaFuncAttributeMaxDynamicSharedMemorySize, SMEM_TOTAL);
    main_kernel<<<dim3(4, NB), NTHR, SMEM_TOTAL>>>(X, bl, out);
}

// round 17
// speedup vs baseline: 1.2121x; 1.2121x over previous
#include <cuda_runtime.h>
#include <cuda_bf16.h>
#include <math.h>
#include <stdint.h>

#define NB 32
#define NT 128
#define NF 128

#define SP 136                   // bf16 per row (128 + 8 pad); SP*2=272B
#define TILE_HI   (128 * SP * 2) // 34816 B
#define TILE_PAIR (2 * TILE_HI)  // 69632 B
#define STRIP_HI  (32 * SP * 2)  // 8704 B
#define STRIP_PAIR (2 * STRIP_HI)

#define NTHR 512

// Prepped images: XA per batch + weights
__device__ __align__(16) unsigned char g_XA[NB][TILE_PAIR];  // [t][f] hi/lo
__device__ __align__(16) unsigned char g_Wd[TILE_PAIR];      // [j][f]
__device__ __align__(16) unsigned char g_Wk[3][TILE_PAIR];   // [u][f] zi/zc/zo

__device__ __forceinline__ float sigf(float x) { return 1.0f / (1.0f + __expf(-x)); }

// ---------------------------------------------------------------------------
// Prep: X (row-major) + Wd + Wk -> bf16 hi/lo images (36 tiles)
// ---------------------------------------------------------------------------
__global__ void prep_kernel(const float* __restrict__ X, const float* __restrict__ Wd,
                            const float* __restrict__ Wk)
{
    int gid = blockIdx.x * blockDim.x + threadIdx.x;
    const int total = 36 * 2048;
    for (int idx = gid; idx < total; idx += gridDim.x * blockDim.x) {
        int tile = idx >> 11;
        int r, chunk;
        if (tile < 32) { chunk = idx & 15; r = (idx >> 4) & 127; }   // coalesced X reads
        else           { r = idx & 127;   chunk = (idx >> 7) & 15; }
        int c0 = chunk * 8;
        float v[8];
        unsigned char* dst;
        if (tile < 32) {
            const float* Xb = X + tile * NT * NF;
#pragma unroll
            for (int q = 0; q < 8; q++) v[q] = Xb[r * NF + c0 + q];
            dst = g_XA[tile];
        } else if (tile == 32) {
#pragma unroll
            for (int q = 0; q < 8; q++) v[q] = Wd[(c0 + q) * NT + r];
            dst = g_Wd;
        } else {
            int gt = tile - 33;
            int gof = (gt == 0) ? 0 : (gt == 1 ? 256 : 384);
#pragma unroll
            for (int q = 0; q < 8; q++) v[q] = Wk[(c0 + q) * 512 + gof + r];
            dst = g_Wk[gt];
        }
        unsigned short hi[8], lo[8];
#pragma unroll
        for (int q = 0; q < 8; q++) {
            __nv_bfloat16 h = __float2bfloat16(v[q]);
            __nv_bfloat16 l = __float2bfloat16(v[q] - __bfloat162float(h));
            hi[q] = *(unsigned short*)&h;
            lo[q] = *(unsigned short*)&l;
        }
        uint32_t off = (uint32_t)(r * SP + c0) * 2;
        *(uint4*)(dst + off) = *(uint4*)hi;
        *(uint4*)(dst + TILE_HI + off) = *(uint4*)lo;
    }
}

// ---------------------------------------------------------------------------
// PTX helpers (all sm_80-baseline)
// ---------------------------------------------------------------------------
__device__ __forceinline__ void mma16816(float* d, uint32_t a0, uint32_t a1,
                                         uint32_t a2, uint32_t a3,
                                         uint32_t b0, uint32_t b1) {
    asm volatile(
        "mma.sync.aligned.m16n8k16.row.col.f32.bf16.bf16.f32 "
        "{%0,%1,%2,%3}, {%4,%5,%6,%7}, {%8,%9}, {%0,%1,%2,%3};"
        : "+f"(d[0]), "+f"(d[1]), "+f"(d[2]), "+f"(d[3])
        : "r"(a0), "r"(a1), "r"(a2), "r"(a3), "r"(b0), "r"(b1));
}
__device__ __forceinline__ uint32_t lds32(const __nv_bfloat16* p) {
    return *(const uint32_t*)p;
}
__device__ __forceinline__ void ldm_x2_t(uint32_t& r0, uint32_t& r1, uint32_t saddr) {
    asm volatile("ldmatrix.sync.aligned.m8n8.x2.trans.shared.b16 {%0,%1}, [%2];"
                 : "=r"(r0), "=r"(r1) : "r"(saddr));
}
__device__ __forceinline__ void cpa16(unsigned char* dst, const unsigned char* src) {
    uint32_t d = (uint32_t)__cvta_generic_to_shared(dst);
    asm volatile("cp.async.cg.shared.global [%0], [%1], 16;" :: "r"(d), "l"(src));
}
#define CPA_COMMIT() asm volatile("cp.async.commit_group;" ::: "memory")
#define CPA_WAIT(n)  asm volatile("cp.async.wait_group %0;" :: "n"(n) : "memory")

__device__ __forceinline__ void cpa_tile(unsigned char* dst, const unsigned char* src,
                                         int bytes, int tid) {
    for (int i = tid * 16; i < bytes; i += NTHR * 16) cpa16(dst + i, src + i);
}

// SMEM layout (bytes)
#define SM_XA  0                          // XA hi/lo -> Wk1
#define SM_WK  TILE_PAIR                  // Wk0 -> Wk2
#define SM_WD  (2 * TILE_PAIR)            // 139264
#define SM_P   (SM_WD + STRIP_PAIR)       // 156672
#define SM_CTX (SM_P + STRIP_PAIR)        // 174080 (Sbuf f32 aliases pre-G2)
#define SMEM_TOTAL (SM_CTX + STRIP_PAIR)  // 191488

// hoisted-A 3-term K=128 pass, direct B loads (row-major [n][k])
__device__ __forceinline__ void gemm3h(float acc[2][4],
                                       const __nv_bfloat16* Ah, const __nv_bfloat16* Al,
                                       const __nv_bfloat16* Bh, const __nv_bfloat16* Bl,
                                       int arow, int brow0, int g, int tq) {
    const __nv_bfloat16* arh = Ah + (arow + g) * SP + 2 * tq;
    const __nv_bfloat16* arl = Al + (arow + g) * SP + 2 * tq;
#pragma unroll
    for (int k0 = 0; k0 < 128; k0 += 16) {
        uint32_t ah0 = lds32(arh + k0), ah1 = lds32(arh + 8 * SP + k0);
        uint32_t ah2 = lds32(arh + k0 + 8), ah3 = lds32(arh + 8 * SP + k0 + 8);
        uint32_t al0 = lds32(arl + k0), al1 = lds32(arl + 8 * SP + k0);
        uint32_t al2 = lds32(arl + k0 + 8), al3 = lds32(arl + 8 * SP + k0 + 8);
#pragma unroll
        for (int nt = 0; nt < 2; nt++) {
            const __nv_bfloat16* brh = Bh + (brow0 + nt * 8 + g) * SP + 2 * tq + k0;
            const __nv_bfloat16* brl = Bl + (brow0 + nt * 8 + g) * SP + 2 * tq + k0;
            uint32_t bh0 = lds32(brh), bh1 = lds32(brh + 8);
            uint32_t bl0 = lds32(brl), bl1 = lds32(brl + 8);
            mma16816(acc[nt], ah0, ah1, ah2, ah3, bh0, bh1);
            mma16816(acc[nt], ah0, ah1, ah2, ah3, bl0, bl1);
            mma16816(acc[nt], al0, al1, al2, al3, bh0, bh1);
        }
    }
}

// ---------------------------------------------------------------------------
// Main: CTA = (batch b, 32 rows i0..), 512 threads / 16 warps
// ---------------------------------------------------------------------------
__global__ __launch_bounds__(NTHR, 1)
void main_kernel(const float* __restrict__ bl, float* __restrict__ out)
{
    extern __shared__ unsigned char smem[];
    const int tid = threadIdx.x;
    const int w = tid >> 5, lane = tid & 31, g = lane >> 2, tq = lane & 3;
    const int b = blockIdx.y, i0 = blockIdx.x * 32;

    const __nv_bfloat16* XAh = (const __nv_bfloat16*)(smem + SM_XA);
    const __nv_bfloat16* XAl = (const __nv_bfloat16*)(smem + SM_XA + TILE_HI);
    const __nv_bfloat16* WKh = (const __nv_bfloat16*)(smem + SM_WK);
    const __nv_bfloat16* WKl = (const __nv_bfloat16*)(smem + SM_WK + TILE_HI);
    const __nv_bfloat16* WDh = (const __nv_bfloat16*)(smem + SM_WD);
    const __nv_bfloat16* WDl = (const __nv_bfloat16*)(smem + SM_WD + STRIP_HI);
    __nv_bfloat16* Ph = (__nv_bfloat16*)(smem + SM_P);
    __nv_bfloat16* Pl = (__nv_bfloat16*)(smem + SM_P + STRIP_HI);
    __nv_bfloat16* Ch = (__nv_bfloat16*)(smem + SM_CTX);
    __nv_bfloat16* Cl = (__nv_bfloat16*)(smem + SM_CTX + STRIP_HI);
    float* Sbuf = (float*)(smem + SM_CTX);   // aliases CTX; dead after softmax

    // group1: XA pair + Wd strips (87 KB); group2: Wk0 (overlaps G1..G2)
    cpa_tile(smem + SM_XA, g_XA[b], TILE_PAIR, tid);
    cpa_tile(smem + SM_WD, g_Wd + i0 * (SP * 2), STRIP_HI, tid);
    cpa_tile(smem + SM_WD + STRIP_HI, g_Wd + TILE_HI + i0 * (SP * 2), STRIP_HI, tid);
    CPA_COMMIT();
    cpa_tile(smem + SM_WK, g_Wk[0], TILE_PAIR, tid);
    CPA_COMMIT();
    CPA_WAIT(1);
    __syncthreads();

    // ---- G1: S[t][j]. warp w: t-strip (w&7)*16, j-half (w>>3)*16 ----
    {
        float acc[2][4] = {};
        const int t0 = (w & 7) * 16, jh = (w >> 3) * 16;
        gemm3h(acc, XAh, XAl, WDh, WDl, t0, jh, g, tq);
        const int r0 = t0 + g;
#pragma unroll
        for (int nt = 0; nt < 2; nt++) {
            int c = jh + nt * 8 + 2 * tq;
            Sbuf[r0 * 33 + c]     = acc[nt][0];
            Sbuf[r0 * 33 + c + 1] = acc[nt][1];
            Sbuf[(r0 + 8) * 33 + c]     = acc[nt][2];
            Sbuf[(r0 + 8) * 33 + c + 1] = acc[nt][3];
        }
    }
    __syncthreads();

    // ---- softmax over t per column j (16 warps x 2 cols); P[j][t] hi/lo ----
    {
#pragma unroll
        for (int c = 0; c < 2; c++) {
            const int j = w * 2 + c;
            float v[4];
#pragma unroll
            for (int r = 0; r < 4; r++) v[r] = Sbuf[(lane + 32 * r) * 33 + j];
            float m = fmaxf(fmaxf(v[0], v[1]), fmaxf(v[2], v[3]));
#pragma unroll
            for (int o = 16; o > 0; o >>= 1) m = fmaxf(m, __shfl_xor_sync(0xffffffffu, m, o));
            float s = 0.f;
#pragma unroll
            for (int r = 0; r < 4; r++) { v[r] = __expf(v[r] - m); s += v[r]; }
#pragma unroll
            for (int o = 16; o > 0; o >>= 1) s += __shfl_xor_sync(0xffffffffu, s, o);
            const float inv = 1.0f / s;
#pragma unroll
            for (int r = 0; r < 4; r++) {
                float a = v[r] * inv;
                __nv_bfloat16 h = __float2bfloat16(a);
                __nv_bfloat16 l = __float2bfloat16(a - __bfloat162float(h));
                Ph[j * SP + lane + 32 * r] = h;
                Pl[j * SP + lane + 32 * r] = l;
            }
        }
    }
    __syncthreads();   // Sbuf dead; P visible

    // ---- G2: CTX[i][f] = P @ X. A=P direct; B=XA via ldmatrix.trans ----
    const int mw = (w & 1) * 16;
    const int n0 = (w >> 1) * 16;
    {
        uint32_t xaH = (uint32_t)__cvta_generic_to_shared(smem + SM_XA)
                       + (uint32_t)((lane & 15) * SP * 2);
        uint32_t xaL = xaH + TILE_HI;
        const __nv_bfloat16* arh = Ph + (mw + g) * SP + 2 * tq;
        const __nv_bfloat16* arl = Pl + (mw + g) * SP + 2 * tq;
        float acc[2][4] = {};
#pragma unroll
        for (int k0 = 0; k0 < 128; k0 += 16) {
            uint32_t ah0 = lds32(arh + k0), ah1 = lds32(arh + 8 * SP + k0);
            uint32_t ah2 = lds32(arh + k0 + 8), ah3 = lds32(arh + 8 * SP + k0 + 8);
            uint32_t al0 = lds32(arl + k0), al1 = lds32(arl + 8 * SP + k0);
            uint32_t al2 = lds32(arl + k0 + 8), al3 = lds32(arl + 8 * SP + k0 + 8);
#pragma unroll
            for (int nt = 0; nt < 2; nt++) {
                uint32_t off = (uint32_t)((k0 * SP + n0 + nt * 8) * 2);
                uint32_t bh0, bh1, bl0, bl1;
                ldm_x2_t(bh0, bh1, xaH + off);
                ldm_x2_t(bl0, bl1, xaL + off);
                mma16816(acc[nt], ah0, ah1, ah2, ah3, bh0, bh1);
                mma16816(acc[nt], ah0, ah1, ah2, ah3, bl0, bl1);
                mma16816(acc[nt], al0, al1, al2, al3, bh0, bh1);
            }
        }
        const int r0 = mw + g;
#pragma unroll
        for (int nt = 0; nt < 2; nt++) {
            int c = n0 + nt * 8 + 2 * tq;
#pragma unroll
            for (int q = 0; q < 4; q++) {
                int rr = (q < 2) ? r0 : r0 + 8;
                int cc = c + (q & 1);
                float x = acc[nt][q];
                __nv_bfloat16 h = __float2bfloat16(x);
                __nv_bfloat16 l = __float2bfloat16(x - __bfloat162float(h));
                Ch[rr * SP + cc] = h;
                Cl[rr * SP + cc] = l;
            }
        }
    }
    __syncthreads();   // XA reads done; CTX visible

    // prefetch Wk1 into (dead) XA region; overlaps gate0
    cpa_tile((unsigned char*)smem + SM_XA, g_Wk[1], TILE_PAIR, tid);
    CPA_COMMIT();

    CPA_WAIT(1);       // Wk0 resident (Wk1 pending)
    __syncthreads();
    float aI[2][4] = {}, aC[2][4] = {}, aO[2][4] = {};
    gemm3h(aI, Ch, Cl, WKh, WKl, mw, n0, g, tq);
    __syncthreads();   // WK reads done

    // prefetch Wk2 into WK region; overlaps gate1
    cpa_tile((unsigned char*)smem + SM_WK, g_Wk[2], TILE_PAIR, tid);
    CPA_COMMIT();

    CPA_WAIT(1);       // Wk1 resident (Wk2 pending)
    __syncthreads();
    gemm3h(aC, Ch, Cl, XAh, XAl, mw, n0, g, tq);

    CPA_WAIT(0);       // Wk2 resident
    __syncthreads();
    gemm3h(aO, Ch, Cl, WKh, WKl, mw, n0, g, tq);

    // ---- epilogue: bias + LSTM cell ----
    {
        const int r0 = i0 + mw + g;
#pragma unroll
        for (int nt = 0; nt < 2; nt++) {
            int u0 = n0 + nt * 8 + 2 * tq;
#pragma unroll
            for (int q = 0; q < 4; q++) {
                int rr = (q < 2) ? r0 : r0 + 8;
                int u = u0 + (q & 1);
                float zi = aI[nt][q] + __ldg(&bl[u]);
                float zc = aC[nt][q] + __ldg(&bl[256 + u]);
                float zo = aO[nt][q] + __ldg(&bl[384 + u]);
                float cell = sigf(zi) * tanhf(zc);
                out[(b * NT + rr) * NF + u] = sigf(zo) * tanhf(cell);
            }
        }
    }
}

extern "C" void kernel_launch(void* const* d_in, const int* in_sizes, int n_in,
                              void* d_out, int out_size)
{
    const float* X  = (const float*)d_in[0];   // (32,128,128)
    const float* Wd = (const float*)d_in[1];   // (256,128), rows [0:128)
    const float* Wk = (const float*)d_in[3];   // (128,512)
    const float* bl = (const float*)d_in[5];   // (512,)
    float* out = (float*)d_out;                // (32,128,128)

    prep_kernel<<<144, 512>>>(X, Wd, Wk);
    cudaFuncSetAttribute(main_kernel, cudaFuncAttributeMaxDynamicSharedMemorySize, SMEM_TOTAL);
    main_kernel<<<dim3(4, NB), NTHR, SMEM_TOTAL>>>(bl, out);
}